// round 3
// baseline (speedup 1.0000x reference)
#include <cuda_runtime.h>
#include <cstdint>
#include <math.h>

#define NHID   1024
#define LSTEPS 1024
#define TPB    64           // 2 warps per CTA, one CTA per batch row
#define NPT    16           // neurons per thread (contiguous)
#define NPAIR  8            // f32x2 pairs per thread

typedef unsigned long long u64;

// ---- packed f32x2 ops (sm_100+) ----
__device__ __forceinline__ float2 ffma2(float2 a, float2 b, float2 c) {
    float2 d;
    asm("fma.rn.f32x2 %0, %1, %2, %3;"
        : "=l"(*(u64*)&d) : "l"(*(u64*)&a), "l"(*(u64*)&b), "l"(*(u64*)&c));
    return d;
}
__device__ __forceinline__ float2 fadd2(float2 a, float2 b) {
    float2 d;
    asm("add.rn.f32x2 %0, %1, %2;"
        : "=l"(*(u64*)&d) : "l"(*(u64*)&a), "l"(*(u64*)&b));
    return d;
}
__device__ __forceinline__ float2 fmul2(float2 a, float2 b) {
    float2 d;
    asm("mul.rn.f32x2 %0, %1, %2;"
        : "=l"(*(u64*)&d) : "l"(*(u64*)&a), "l"(*(u64*)&b));
    return d;
}

// Barrier + OR-reduction across the CTA in ONE instruction (BAR.RED).
// Synchronizes (orders smem) and returns OR of p over all threads.
__device__ __forceinline__ bool bar_red_or(bool p) {
    unsigned r;
    asm volatile(
        "{\n\t"
        ".reg .pred pi, po;\n\t"
        "setp.ne.u32 pi, %1, 0;\n\t"
        "bar.red.or.pred po, 0, pi;\n\t"
        "selp.u32 %0, 1, 0, po;\n\t"
        "}"
        : "=r"(r) : "r"((unsigned)p) : "memory");
    return r != 0;
}

// One CTA = one batch row. Thread owns neurons [16*tid, 16*tid+16) as 8 f32x2
// pairs. Cold loop: no spikes have ever occurred -> ref/ft/fts are exactly 0,
// no recurrent input; only lif/hy/hz evolve (registers). One bar.red per step
// both syncs and broadcasts "spiked this step". Hot loop (general, smem-backed
// ref/ft/fts + mask gather) runs only after the first RF spike.
__global__ __launch_bounds__(TPB)
void coesn_kernel(const float* __restrict__ x,      // (B, L)
                  const float* __restrict__ x2h,    // (NHID)
                  const float* __restrict__ h2h,    // (NHID, NHID)
                  const float* __restrict__ bias,   // (NHID)
                  const float* __restrict__ gamma_, // (NHID)
                  const float* __restrict__ eps_,   // (NHID)
                  const float* __restrict__ sgain,  // scalar
                  float* __restrict__ out)          // (B, 2*NHID)
{
    __shared__ float    xs[LSTEPS];
    __shared__ unsigned smask[TPB];   // 16-bit spike mask per thread
    __shared__ float    sref[NHID], sft[NHID], sfts[NHID];

    const int tid = threadIdx.x;
    const int b   = blockIdx.x;

    // Stage this row's 1024 inputs into smem.
    {
        const float4* xr = (const float4*)(x + (size_t)b * LSTEPS);
        #pragma unroll
        for (int i = 0; i < 4; ++i)
            ((float4*)xs)[tid + i * TPB] = xr[tid + i * TPB];
    }

    // ---- constants ----
    const float dt = 0.01f;
    const float A  = 1.0f - dt / 20.0f;          // LIF decay (1 - dt/LIF_TAU_M)
    const float sg = *sgain;
    const float RD = expf(-dt / 0.25f);          // refractory decay
    const float FD = expf(-dt / 10.0f);          // filter decay

    const float2 A2     = make_float2(A, A);
    const float2 DT2    = make_float2(dt, dt);
    const float2 NDTSG2 = make_float2(-dt * sg, -dt * sg);
    const float2 RD2    = make_float2(RD, RD);
    const float2 FD2    = make_float2(FD, FD);

    float2 W2[NPAIR], B2[NPAIR], EZ2[NPAIR], GN2[NPAIR];
    #pragma unroll
    for (int i = 0; i < 4; ++i) {
        float4 a;
        a = ((const float4*)x2h)[tid * 4 + i];
        W2[2*i]   = make_float2(dt*a.x, dt*a.y);
        W2[2*i+1] = make_float2(dt*a.z, dt*a.w);
        a = ((const float4*)bias)[tid * 4 + i];
        B2[2*i]   = make_float2(dt*a.x, dt*a.y);
        B2[2*i+1] = make_float2(dt*a.z, dt*a.w);
        a = ((const float4*)eps_)[tid * 4 + i];
        EZ2[2*i]   = make_float2(1.f-dt*a.x, 1.f-dt*a.y);
        EZ2[2*i+1] = make_float2(1.f-dt*a.z, 1.f-dt*a.w);
        a = ((const float4*)gamma_)[tid * 4 + i];
        GN2[2*i]   = make_float2(-dt*a.x, -dt*a.y);
        GN2[2*i+1] = make_float2(-dt*a.z, -dt*a.w);
    }

    float2 lif2[NPAIR], hy2[NPAIR], hz2[NPAIR];
    #pragma unroll
    for (int p = 0; p < NPAIR; ++p) {
        lif2[p] = make_float2(0.f, 0.f);
        hy2[p]  = make_float2(0.f, 0.f);
        hz2[p]  = make_float2(0.f, 0.f);
    }

    __syncthreads();   // xs ready

    int  t      = 0;
    bool spiked = false;   // CTA ever had an RF spike

    // =================== COLD LOOP (no RF spike yet) ===================
    #pragma unroll 1
    for (; t < LSTEPS; ++t) {
        const float  xt  = xs[t];
        const float2 XT2 = make_float2(xt, xt);

        float m[NPAIR];
        #pragma unroll
        for (int p = 0; p < NPAIR; ++p) {
            float2 I = ffma2(XT2, W2[p], B2[p]);            // dt*(xt*w + bias)
            lif2[p] = ffma2(lif2[p], A2, I);                // v = v*A + dt*I
            const bool l0 = lif2[p].x > 1.0f;
            const bool l1 = lif2[p].y > 1.0f;
            float2 ms = make_float2(l0 ? -1.0f : 0.0f, l1 ? -1.0f : 0.0f);
            lif2[p] = fadd2(lif2[p], ms);                   // soft reset
            float2 k = fmul2(ms, NDTSG2);                   // +dt*sg on spike
            hz2[p] = ffma2(hz2[p], EZ2[p], ffma2(GN2[p], hy2[p], k));
            hy2[p] = ffma2(DT2, hz2[p], hy2[p]);
            m[p] = fmaxf(hy2[p].x, hy2[p].y);
        }
        // max-tree over this thread's 16 hy values
        float mx = fmaxf(fmaxf(fmaxf(m[0], m[1]), fmaxf(m[2], m[3])),
                         fmaxf(fmaxf(m[4], m[5]), fmaxf(m[6], m[7])));
        // in cold regime ref==0, so spike <=> (hy-1)>0 <=> hy>1 (exact, Sterbenz)
        const bool fire = mx > 1.0f;
        if (bar_red_or(fire)) {
            // transition step: exact per-neuron spikes (ref==0), init smem state
            unsigned msk = 0;
            #pragma unroll
            for (int p = 0; p < NPAIR; ++p) {
                const bool q0 = hy2[p].x > 1.0f;
                const bool q1 = hy2[p].y > 1.0f;
                const float s0 = q0 ? 1.0f : 0.0f;
                const float s1 = q1 ? 1.0f : 0.0f;
                const int n = tid * NPT + 2 * p;
                sref[n]   = s0;  sref[n+1] = s1;   // 0*RD + s
                sft[n]    = s0;  sft[n+1]  = s1;   // 0*FD + s
                sfts[n]   = s0;  sfts[n+1] = s1;   // fts += ft
                msk |= (q0 ? 1u : 0u) << (2 * p);
                msk |= (q1 ? 1u : 0u) << (2 * p + 1);
            }
            smask[tid] = msk;
            spiked = true;
            ++t;
            break;
        }
    }

    // =================== HOT LOOP (general path; rare) ===================
    if (spiked) {
        bool prev = true;   // spikes occurred at step t-1
        __syncthreads();    // smask/sref/sft/sfts visible
        #pragma unroll 1
        for (; t < LSTEPS; ++t) {
            const float  xt  = xs[t];
            const float2 XT2 = make_float2(xt, xt);

            float2 acc[NPAIR];
            #pragma unroll
            for (int p = 0; p < NPAIR; ++p) acc[p] = make_float2(0.f, 0.f);

            if (prev) {   // gather h2h rows of neurons that spiked last step
                for (int w = 0; w < TPB; ++w) {
                    unsigned mm = smask[w];
                    while (mm) {
                        const int k = __ffs(mm) - 1; mm &= mm - 1;
                        const int j = w * NPT + k;
                        const float4* hp =
                            (const float4*)(h2h + (size_t)j * NHID + tid * NPT);
                        #pragma unroll
                        for (int i = 0; i < 4; ++i) {
                            float4 h = __ldg(hp + i);
                            acc[2*i].x   += h.x; acc[2*i].y   += h.y;
                            acc[2*i+1].x += h.z; acc[2*i+1].y += h.w;
                        }
                    }
                }
            }

            bool any = false;
            unsigned msk = 0;
            #pragma unroll
            for (int p = 0; p < NPAIR; ++p) {
                float2 I = ffma2(XT2, W2[p], B2[p]);
                I = ffma2(DT2, acc[p], I);
                lif2[p] = ffma2(lif2[p], A2, I);
                const bool l0 = lif2[p].x > 1.0f;
                const bool l1 = lif2[p].y > 1.0f;
                float2 ms = make_float2(l0 ? -1.0f : 0.0f, l1 ? -1.0f : 0.0f);
                lif2[p] = fadd2(lif2[p], ms);
                float2 k = fmul2(ms, NDTSG2);
                hz2[p] = ffma2(hz2[p], EZ2[p], ffma2(GN2[p], hy2[p], k));
                hy2[p] = ffma2(DT2, hz2[p], hy2[p]);

                const int n = tid * NPT + 2 * p;
                float2 rf = make_float2(sref[n], sref[n+1]);
                const bool q0 = (hy2[p].x - 1.0f) > rf.x;
                const bool q1 = (hy2[p].y - 1.0f) > rf.y;
                float2 sn = make_float2(q0 ? 1.0f : 0.0f, q1 ? 1.0f : 0.0f);
                rf = ffma2(rf, RD2, sn);
                sref[n] = rf.x; sref[n+1] = rf.y;
                float2 f = make_float2(sft[n], sft[n+1]);
                f = ffma2(f, FD2, sn);
                sft[n] = f.x; sft[n+1] = f.y;
                sfts[n]   += f.x;
                sfts[n+1] += f.y;
                any = any || q0 || q1;
                msk |= (q0 ? 1u : 0u) << (2 * p);
                msk |= (q1 ? 1u : 0u) << (2 * p + 1);
            }
            smask[tid] = msk;
            prev = bar_red_or(any);   // syncs smem + broadcasts spike flag
        }
    }

    // =================== epilogue: out = concat(fts / L, ft) ===================
    const float invL = 1.0f / (float)LSTEPS;
    float* o0 = out + (size_t)b * (2 * NHID) + tid * NPT;
    float* o1 = o0 + NHID;
    if (!spiked) {
        const float4 z = make_float4(0.f, 0.f, 0.f, 0.f);
        #pragma unroll
        for (int i = 0; i < 4; ++i) { ((float4*)o0)[i] = z; ((float4*)o1)[i] = z; }
    } else {
        #pragma unroll
        for (int i = 0; i < 4; ++i) {
            const int n = tid * NPT + 4 * i;
            ((float4*)o0)[i] = make_float4(sfts[n]*invL, sfts[n+1]*invL,
                                           sfts[n+2]*invL, sfts[n+3]*invL);
            ((float4*)o1)[i] = make_float4(sft[n], sft[n+1], sft[n+2], sft[n+3]);
        }
    }
}

extern "C" void kernel_launch(void* const* d_in, const int* in_sizes, int n_in,
                              void* d_out, int out_size)
{
    const float* x    = (const float*)d_in[0];
    const float* x2h  = (const float*)d_in[1];
    const float* h2h  = (const float*)d_in[2];
    const float* bias = (const float*)d_in[3];
    const float* gam  = (const float*)d_in[4];
    const float* eps  = (const float*)d_in[5];
    const float* sg   = (const float*)d_in[6];

    const int B = in_sizes[0] / LSTEPS;   // N_INP == 1
    coesn_kernel<<<B, TPB>>>(x, x2h, h2h, bias, gam, eps, sg, (float*)d_out);
}

// round 4
// speedup vs baseline: 1.5851x; 1.5851x over previous
#include <cuda_runtime.h>
#include <cstdint>
#include <math.h>

#define NHID   1024
#define LSTEPS 1024
#define TPB    128          // 4 warps per CTA, one CTA per batch row
#define NPT    8            // neurons per thread (contiguous)
#define NPAIR  4            // f32x2 pairs per thread

typedef unsigned long long u64;

// ---- packed f32x2 ops (sm_100+) ----
__device__ __forceinline__ float2 ffma2(float2 a, float2 b, float2 c) {
    float2 d;
    asm("fma.rn.f32x2 %0, %1, %2, %3;"
        : "=l"(*(u64*)&d) : "l"(*(u64*)&a), "l"(*(u64*)&b), "l"(*(u64*)&c));
    return d;
}
__device__ __forceinline__ float2 fadd2(float2 a, float2 b) {
    float2 d;
    asm("add.rn.f32x2 %0, %1, %2;"
        : "=l"(*(u64*)&d) : "l"(*(u64*)&a), "l"(*(u64*)&b));
    return d;
}
__device__ __forceinline__ float2 fmul2(float2 a, float2 b) {
    float2 d;
    asm("mul.rn.f32x2 %0, %1, %2;"
        : "=l"(*(u64*)&d) : "l"(*(u64*)&a), "l"(*(u64*)&b));
    return d;
}

// Barrier + OR-reduction across the CTA in one BAR.RED instruction.
__device__ __forceinline__ bool bar_red_or(bool p) {
    unsigned r;
    asm volatile(
        "{\n\t"
        ".reg .pred pi, po;\n\t"
        "setp.ne.u32 pi, %1, 0;\n\t"
        "bar.red.or.pred po, 0, pi;\n\t"
        "selp.u32 %0, 1, 0, po;\n\t"
        "}"
        : "=r"(r) : "r"((unsigned)p) : "memory");
    return r != 0;
}

// One CTA = one batch row. Thread owns neurons [8*tid, 8*tid+8) as 4 f32x2
// pairs.
//
// COLD PASS (barrier-free): while no RF spike has EVER occurred in this row,
// ref/ft/fts are exactly 0 and there is no recurrent coupling. alpha=beta=0
// means an RF spike would not alter hy/hz either, so the uncoupled hy
// trajectory is valid up to and including the first crossing. Each thread
// evolves lif/hy/hz in registers, tracks running max(hy), and ONE bar.red at
// the end decides whether any neuron ever crossed hy>1 (ref==0 => spike
// condition (hy-1-ref)>0 <=> hy>1, exact).
//
// FALLBACK (general, coupled): only if a spike occurred. Re-runs the row from
// t=0 with smem-resident ref/ft/fts, spike-mask exchange and h2h row gather.
__global__ __launch_bounds__(TPB, 4)
void coesn_kernel(const float* __restrict__ x,      // (B, L)
                  const float* __restrict__ x2h,    // (NHID)
                  const float* __restrict__ h2h,    // (NHID, NHID)
                  const float* __restrict__ bias,   // (NHID)
                  const float* __restrict__ gamma_, // (NHID)
                  const float* __restrict__ eps_,   // (NHID)
                  const float* __restrict__ sgain,  // scalar
                  float* __restrict__ out)          // (B, 2*NHID)
{
    __shared__ float    xs[LSTEPS];
    __shared__ unsigned smask[TPB];                 // fallback only
    __shared__ float    sref[NHID], sft[NHID], sfts[NHID];  // fallback only

    const int tid = threadIdx.x;
    const int b   = blockIdx.x;

    // Stage this row's 1024 inputs into smem (two float4 per thread).
    {
        const float4* xr = (const float4*)(x + (size_t)b * LSTEPS);
        ((float4*)xs)[tid]       = xr[tid];
        ((float4*)xs)[tid + TPB] = xr[tid + TPB];
    }

    // ---- constants ----
    const float dt = 0.01f;
    const float A  = 1.0f - dt / 20.0f;             // LIF decay
    const float sg = *sgain;
    const float RD = expf(-dt / 0.25f);             // refractory decay
    const float FD = expf(-dt / 10.0f);             // filter decay

    const float2 A2     = make_float2(A, A);
    const float2 DT2    = make_float2(dt, dt);
    const float2 NDTSG2 = make_float2(-dt * sg, -dt * sg);
    const float2 RD2    = make_float2(RD, RD);
    const float2 FD2    = make_float2(FD, FD);

    float2 W2[NPAIR], B2[NPAIR], EZ2[NPAIR], GN2[NPAIR];
    #pragma unroll
    for (int i = 0; i < 2; ++i) {
        float4 a;
        a = ((const float4*)x2h)[tid * 2 + i];
        W2[2*i]   = make_float2(dt*a.x, dt*a.y);
        W2[2*i+1] = make_float2(dt*a.z, dt*a.w);
        a = ((const float4*)bias)[tid * 2 + i];
        B2[2*i]   = make_float2(dt*a.x, dt*a.y);
        B2[2*i+1] = make_float2(dt*a.z, dt*a.w);
        a = ((const float4*)eps_)[tid * 2 + i];
        EZ2[2*i]   = make_float2(1.f-dt*a.x, 1.f-dt*a.y);
        EZ2[2*i+1] = make_float2(1.f-dt*a.z, 1.f-dt*a.w);
        a = ((const float4*)gamma_)[tid * 2 + i];
        GN2[2*i]   = make_float2(-dt*a.x, -dt*a.y);
        GN2[2*i+1] = make_float2(-dt*a.z, -dt*a.w);
    }

    float2 lif2[NPAIR], hy2[NPAIR], hz2[NPAIR], mx2[NPAIR];
    #pragma unroll
    for (int p = 0; p < NPAIR; ++p) {
        lif2[p] = make_float2(0.f, 0.f);
        hy2[p]  = make_float2(0.f, 0.f);
        hz2[p]  = make_float2(0.f, 0.f);
        mx2[p]  = make_float2(-1.f, -1.f);
    }

    __syncthreads();   // xs ready

    // =================== COLD PASS: no barriers, registers only ===========
    #pragma unroll 1
    for (int tq = 0; tq < LSTEPS / 4; ++tq) {
        const float4 xq = ((const float4*)xs)[tq];
        const float xtv[4] = {xq.x, xq.y, xq.z, xq.w};
        #pragma unroll
        for (int s = 0; s < 4; ++s) {
            const float2 XT2 = make_float2(xtv[s], xtv[s]);
            #pragma unroll
            for (int p = 0; p < NPAIR; ++p) {
                float2 I = ffma2(XT2, W2[p], B2[p]);        // dt*(xt*w + b)
                lif2[p] = ffma2(lif2[p], A2, I);            // v = v*A + dt*I
                const bool l0 = lif2[p].x > 1.0f;
                const bool l1 = lif2[p].y > 1.0f;
                float2 ms = make_float2(l0 ? -1.0f : 0.0f, l1 ? -1.0f : 0.0f);
                lif2[p] = fadd2(lif2[p], ms);               // soft reset
                float2 k = fmul2(ms, NDTSG2);               // +dt*sg on spike
                hz2[p] = ffma2(hz2[p], EZ2[p], ffma2(GN2[p], hy2[p], k));
                hy2[p] = ffma2(DT2, hz2[p], hy2[p]);
                mx2[p].x = fmaxf(mx2[p].x, hy2[p].x);
                mx2[p].y = fmaxf(mx2[p].y, hy2[p].y);
            }
        }
    }

    float mm = fmaxf(fmaxf(fmaxf(mx2[0].x, mx2[0].y), fmaxf(mx2[1].x, mx2[1].y)),
                     fmaxf(fmaxf(mx2[2].x, mx2[2].y), fmaxf(mx2[3].x, mx2[3].y)));
    const bool ever = bar_red_or(mm > 1.0f);

    float* o0 = out + (size_t)b * (2 * NHID) + tid * NPT;
    float* o1 = o0 + NHID;

    if (!ever) {
        // No RF spike in the entire row: ft == fts == 0 exactly.
        const float4 z = make_float4(0.f, 0.f, 0.f, 0.f);
        ((float4*)o0)[0] = z; ((float4*)o0)[1] = z;
        ((float4*)o1)[0] = z; ((float4*)o1)[1] = z;
        return;
    }

    // =================== FALLBACK: full coupled dynamics from t=0 =========
    #pragma unroll
    for (int p = 0; p < NPAIR; ++p) {
        lif2[p] = make_float2(0.f, 0.f);
        hy2[p]  = make_float2(0.f, 0.f);
        hz2[p]  = make_float2(0.f, 0.f);
    }
    #pragma unroll
    for (int q = 0; q < NPT; ++q) {
        const int n = tid * NPT + q;
        sref[n] = 0.f; sft[n] = 0.f; sfts[n] = 0.f;
    }
    smask[tid] = 0u;
    __syncthreads();

    bool prev = false;   // spikes at step t-1?
    #pragma unroll 1
    for (int t = 0; t < LSTEPS; ++t) {
        const float  xt  = xs[t];
        const float2 XT2 = make_float2(xt, xt);

        float2 acc[NPAIR];
        #pragma unroll
        for (int p = 0; p < NPAIR; ++p) acc[p] = make_float2(0.f, 0.f);

        if (prev) {   // gather h2h rows of neurons that spiked last step
            for (int w = 0; w < TPB; ++w) {
                unsigned mm_ = smask[w];
                while (mm_) {
                    const int k = __ffs(mm_) - 1; mm_ &= mm_ - 1;
                    const int j = w * NPT + k;
                    const float4* hp =
                        (const float4*)(h2h + (size_t)j * NHID + tid * NPT);
                    #pragma unroll
                    for (int i = 0; i < 2; ++i) {
                        float4 h = __ldg(hp + i);
                        acc[2*i].x   += h.x; acc[2*i].y   += h.y;
                        acc[2*i+1].x += h.z; acc[2*i+1].y += h.w;
                    }
                }
            }
        }

        bool any = false;
        unsigned msk = 0;
        #pragma unroll
        for (int p = 0; p < NPAIR; ++p) {
            float2 I = ffma2(XT2, W2[p], B2[p]);
            I = ffma2(DT2, acc[p], I);
            lif2[p] = ffma2(lif2[p], A2, I);
            const bool l0 = lif2[p].x > 1.0f;
            const bool l1 = lif2[p].y > 1.0f;
            float2 ms = make_float2(l0 ? -1.0f : 0.0f, l1 ? -1.0f : 0.0f);
            lif2[p] = fadd2(lif2[p], ms);
            float2 k = fmul2(ms, NDTSG2);
            hz2[p] = ffma2(hz2[p], EZ2[p], ffma2(GN2[p], hy2[p], k));
            hy2[p] = ffma2(DT2, hz2[p], hy2[p]);

            const int n = tid * NPT + 2 * p;
            float2 rf = make_float2(sref[n], sref[n+1]);
            const bool q0 = (hy2[p].x - 1.0f) > rf.x;
            const bool q1 = (hy2[p].y - 1.0f) > rf.y;
            float2 sn = make_float2(q0 ? 1.0f : 0.0f, q1 ? 1.0f : 0.0f);
            rf = ffma2(rf, RD2, sn);
            sref[n] = rf.x; sref[n+1] = rf.y;
            float2 f = make_float2(sft[n], sft[n+1]);
            f = ffma2(f, FD2, sn);
            sft[n] = f.x; sft[n+1] = f.y;
            sfts[n]   += f.x;
            sfts[n+1] += f.y;
            any = any || q0 || q1;
            msk |= (q0 ? 1u : 0u) << (2 * p);
            msk |= (q1 ? 1u : 0u) << (2 * p + 1);
        }
        smask[tid] = msk;
        prev = bar_red_or(any);   // syncs smem + broadcasts spike flag
    }

    const float invL = 1.0f / (float)LSTEPS;
    #pragma unroll
    for (int i = 0; i < 2; ++i) {
        const int n = tid * NPT + 4 * i;
        ((float4*)o0)[i] = make_float4(sfts[n]*invL, sfts[n+1]*invL,
                                       sfts[n+2]*invL, sfts[n+3]*invL);
        ((float4*)o1)[i] = make_float4(sft[n], sft[n+1], sft[n+2], sft[n+3]);
    }
}

extern "C" void kernel_launch(void* const* d_in, const int* in_sizes, int n_in,
                              void* d_out, int out_size)
{
    const float* x    = (const float*)d_in[0];
    const float* x2h  = (const float*)d_in[1];
    const float* h2h  = (const float*)d_in[2];
    const float* bias = (const float*)d_in[3];
    const float* gam  = (const float*)d_in[4];
    const float* eps  = (const float*)d_in[5];
    const float* sg   = (const float*)d_in[6];

    const int B = in_sizes[0] / LSTEPS;   // N_INP == 1
    coesn_kernel<<<B, TPB>>>(x, x2h, h2h, bias, gam, eps, sg, (float*)d_out);
}

// round 5
// speedup vs baseline: 1.6558x; 1.0446x over previous
#include <cuda_runtime.h>
#include <cstdint>
#include <math.h>

#define NHID   1024
#define LSTEPS 1024
#define TPB    128          // 4 warps per CTA, one CTA per batch row
#define NPT    8            // neurons per thread (contiguous)
#define NPAIR  4            // f32x2 pairs per thread

typedef unsigned long long u64;

// ---- packed f32x2 ops (sm_100+) ----
__device__ __forceinline__ float2 ffma2(float2 a, float2 b, float2 c) {
    float2 d;
    asm("fma.rn.f32x2 %0, %1, %2, %3;"
        : "=l"(*(u64*)&d) : "l"(*(u64*)&a), "l"(*(u64*)&b), "l"(*(u64*)&c));
    return d;
}
__device__ __forceinline__ float2 fadd2(float2 a, float2 b) {
    float2 d;
    asm("add.rn.f32x2 %0, %1, %2;"
        : "=l"(*(u64*)&d) : "l"(*(u64*)&a), "l"(*(u64*)&b));
    return d;
}
__device__ __forceinline__ float2 fmul2(float2 a, float2 b) {
    float2 d;
    asm("mul.rn.f32x2 %0, %1, %2;"
        : "=l"(*(u64*)&d) : "l"(*(u64*)&a), "l"(*(u64*)&b));
    return d;
}

// Barrier + OR-reduction across the CTA in one BAR.RED instruction.
__device__ __forceinline__ bool bar_red_or(bool p) {
    unsigned r;
    asm volatile(
        "{\n\t"
        ".reg .pred pi, po;\n\t"
        "setp.ne.u32 pi, %1, 0;\n\t"
        "bar.red.or.pred po, 0, pi;\n\t"
        "selp.u32 %0, 1, 0, po;\n\t"
        "}"
        : "=r"(r) : "r"((unsigned)p) : "memory");
    return r != 0;
}

// One CTA = one batch row. Thread owns neurons [8*tid, 8*tid+8) as 4 f32x2
// pairs.
//
// COLD PASS (barrier-free): while no RF spike has EVER occurred in this row,
// ref/ft/fts are exactly 0 and there is no recurrent coupling. alpha=beta=0
// means an RF spike would not alter hy/hz either, so the uncoupled hy
// trajectory is valid up to and including the first crossing. Each thread
// evolves lif/hy/hz in registers, tracks a running max of all its hy values in
// ONE packed accumulator, and a single bar.red at the end decides whether any
// neuron ever crossed hy>1 (ref==0 => spike condition (hy-1-ref)>0 <=> hy>1,
// exact by Sterbenz).
//
// FALLBACK (general, coupled): only if a spike occurred. Re-runs the row from
// t=0 with smem-resident ref/ft/fts, spike-mask exchange and h2h row gather.
__global__ __launch_bounds__(TPB, 6)
void coesn_kernel(const float* __restrict__ x,      // (B, L)
                  const float* __restrict__ x2h,    // (NHID)
                  const float* __restrict__ h2h,    // (NHID, NHID)
                  const float* __restrict__ bias,   // (NHID)
                  const float* __restrict__ gamma_, // (NHID)
                  const float* __restrict__ eps_,   // (NHID)
                  const float* __restrict__ sgain,  // scalar
                  float* __restrict__ out)          // (B, 2*NHID)
{
    __shared__ float    xs[LSTEPS];
    __shared__ unsigned smask[TPB];                 // fallback only
    __shared__ float    sref[NHID], sft[NHID], sfts[NHID];  // fallback only

    const int tid = threadIdx.x;
    const int b   = blockIdx.x;

    // Stage this row's 1024 inputs into smem (two float4 per thread).
    {
        const float4* xr = (const float4*)(x + (size_t)b * LSTEPS);
        ((float4*)xs)[tid]       = xr[tid];
        ((float4*)xs)[tid + TPB] = xr[tid + TPB];
    }

    // ---- constants ----
    const float dt = 0.01f;
    const float A  = 1.0f - dt / 20.0f;             // LIF decay
    const float sg = *sgain;

    const float2 A2     = make_float2(A, A);
    const float2 DT2    = make_float2(dt, dt);
    const float2 NDTSG2 = make_float2(-dt * sg, -dt * sg);

    float2 W2[NPAIR], B2[NPAIR], EZ2[NPAIR], GN2[NPAIR];
    #pragma unroll
    for (int i = 0; i < 2; ++i) {
        float4 a;
        a = ((const float4*)x2h)[tid * 2 + i];
        W2[2*i]   = make_float2(dt*a.x, dt*a.y);
        W2[2*i+1] = make_float2(dt*a.z, dt*a.w);
        a = ((const float4*)bias)[tid * 2 + i];
        B2[2*i]   = make_float2(dt*a.x, dt*a.y);
        B2[2*i+1] = make_float2(dt*a.z, dt*a.w);
        a = ((const float4*)eps_)[tid * 2 + i];
        EZ2[2*i]   = make_float2(1.f-dt*a.x, 1.f-dt*a.y);
        EZ2[2*i+1] = make_float2(1.f-dt*a.z, 1.f-dt*a.w);
        a = ((const float4*)gamma_)[tid * 2 + i];
        GN2[2*i]   = make_float2(-dt*a.x, -dt*a.y);
        GN2[2*i+1] = make_float2(-dt*a.z, -dt*a.w);
    }

    float2 lif2[NPAIR], hy2[NPAIR], hz2[NPAIR];
    #pragma unroll
    for (int p = 0; p < NPAIR; ++p) {
        lif2[p] = make_float2(0.f, 0.f);
        hy2[p]  = make_float2(0.f, 0.f);
        hz2[p]  = make_float2(0.f, 0.f);
    }
    float2 mx2 = make_float2(-1.f, -1.f);   // running max of hy (packed lanes)

    __syncthreads();   // xs ready

    // =================== COLD PASS: no barriers, registers only ===========
    #pragma unroll 1
    for (int tq = 0; tq < LSTEPS / 8; ++tq) {
        const float4 xa = ((const float4*)xs)[tq * 2];
        const float4 xb = ((const float4*)xs)[tq * 2 + 1];
        const float xtv[8] = {xa.x, xa.y, xa.z, xa.w, xb.x, xb.y, xb.z, xb.w};
        #pragma unroll
        for (int s = 0; s < 8; ++s) {
            const float2 XT2 = make_float2(xtv[s], xtv[s]);
            #pragma unroll
            for (int p = 0; p < NPAIR; ++p) {
                float2 I = ffma2(XT2, W2[p], B2[p]);        // dt*(xt*w + b)
                lif2[p] = ffma2(lif2[p], A2, I);            // v = v*A + dt*I
                const bool l0 = lif2[p].x > 1.0f;
                const bool l1 = lif2[p].y > 1.0f;
                float2 ms = make_float2(l0 ? -1.0f : 0.0f, l1 ? -1.0f : 0.0f);
                lif2[p] = fadd2(lif2[p], ms);               // soft reset
                float2 k = fmul2(ms, NDTSG2);               // +dt*sg on spike
                hz2[p] = ffma2(hz2[p], EZ2[p], ffma2(GN2[p], hy2[p], k));
                hy2[p] = ffma2(DT2, hz2[p], hy2[p]);
                mx2.x = fmaxf(mx2.x, hy2[p].x);
                mx2.y = fmaxf(mx2.y, hy2[p].y);
            }
        }
    }

    const bool ever = bar_red_or(fmaxf(mx2.x, mx2.y) > 1.0f);

    float* o0 = out + (size_t)b * (2 * NHID) + tid * NPT;
    float* o1 = o0 + NHID;

    if (!ever) {
        // No RF spike in the entire row: ft == fts == 0 exactly.
        const float4 z = make_float4(0.f, 0.f, 0.f, 0.f);
        ((float4*)o0)[0] = z; ((float4*)o0)[1] = z;
        ((float4*)o1)[0] = z; ((float4*)o1)[1] = z;
        return;
    }

    // =================== FALLBACK: full coupled dynamics from t=0 =========
    {
        const float RD = expf(-dt / 0.25f);             // refractory decay
        const float FD = expf(-dt / 10.0f);             // filter decay
        const float2 RD2 = make_float2(RD, RD);
        const float2 FD2 = make_float2(FD, FD);

        #pragma unroll
        for (int p = 0; p < NPAIR; ++p) {
            lif2[p] = make_float2(0.f, 0.f);
            hy2[p]  = make_float2(0.f, 0.f);
            hz2[p]  = make_float2(0.f, 0.f);
        }
        #pragma unroll
        for (int q = 0; q < NPT; ++q) {
            const int n = tid * NPT + q;
            sref[n] = 0.f; sft[n] = 0.f; sfts[n] = 0.f;
        }
        smask[tid] = 0u;
        __syncthreads();

        bool prev = false;   // spikes at step t-1?
        #pragma unroll 1
        for (int t = 0; t < LSTEPS; ++t) {
            const float  xt  = xs[t];
            const float2 XT2 = make_float2(xt, xt);

            float2 acc[NPAIR];
            #pragma unroll
            for (int p = 0; p < NPAIR; ++p) acc[p] = make_float2(0.f, 0.f);

            if (prev) {   // gather h2h rows of neurons that spiked last step
                for (int w = 0; w < TPB; ++w) {
                    unsigned mm_ = smask[w];
                    while (mm_) {
                        const int k = __ffs(mm_) - 1; mm_ &= mm_ - 1;
                        const int j = w * NPT + k;
                        const float4* hp =
                            (const float4*)(h2h + (size_t)j * NHID + tid * NPT);
                        #pragma unroll
                        for (int i = 0; i < 2; ++i) {
                            float4 h = __ldg(hp + i);
                            acc[2*i].x   += h.x; acc[2*i].y   += h.y;
                            acc[2*i+1].x += h.z; acc[2*i+1].y += h.w;
                        }
                    }
                }
            }

            bool any = false;
            unsigned msk = 0;
            #pragma unroll
            for (int p = 0; p < NPAIR; ++p) {
                float2 I = ffma2(XT2, W2[p], B2[p]);
                I = ffma2(DT2, acc[p], I);
                lif2[p] = ffma2(lif2[p], A2, I);
                const bool l0 = lif2[p].x > 1.0f;
                const bool l1 = lif2[p].y > 1.0f;
                float2 ms = make_float2(l0 ? -1.0f : 0.0f, l1 ? -1.0f : 0.0f);
                lif2[p] = fadd2(lif2[p], ms);
                float2 k = fmul2(ms, NDTSG2);
                hz2[p] = ffma2(hz2[p], EZ2[p], ffma2(GN2[p], hy2[p], k));
                hy2[p] = ffma2(DT2, hz2[p], hy2[p]);

                const int n = tid * NPT + 2 * p;
                float2 rf = make_float2(sref[n], sref[n+1]);
                const bool q0 = (hy2[p].x - 1.0f) > rf.x;
                const bool q1 = (hy2[p].y - 1.0f) > rf.y;
                float2 sn = make_float2(q0 ? 1.0f : 0.0f, q1 ? 1.0f : 0.0f);
                rf = ffma2(rf, RD2, sn);
                sref[n] = rf.x; sref[n+1] = rf.y;
                float2 f = make_float2(sft[n], sft[n+1]);
                f = ffma2(f, FD2, sn);
                sft[n] = f.x; sft[n+1] = f.y;
                sfts[n]   += f.x;
                sfts[n+1] += f.y;
                any = any || q0 || q1;
                msk |= (q0 ? 1u : 0u) << (2 * p);
                msk |= (q1 ? 1u : 0u) << (2 * p + 1);
            }
            smask[tid] = msk;
            prev = bar_red_or(any);   // syncs smem + broadcasts spike flag
        }

        const float invL = 1.0f / (float)LSTEPS;
        #pragma unroll
        for (int i = 0; i < 2; ++i) {
            const int n = tid * NPT + 4 * i;
            ((float4*)o0)[i] = make_float4(sfts[n]*invL, sfts[n+1]*invL,
                                           sfts[n+2]*invL, sfts[n+3]*invL);
            ((float4*)o1)[i] = make_float4(sft[n], sft[n+1], sft[n+2], sft[n+3]);
        }
    }
}

extern "C" void kernel_launch(void* const* d_in, const int* in_sizes, int n_in,
                              void* d_out, int out_size)
{
    const float* x    = (const float*)d_in[0];
    const float* x2h  = (const float*)d_in[1];
    const float* h2h  = (const float*)d_in[2];
    const float* bias = (const float*)d_in[3];
    const float* gam  = (const float*)d_in[4];
    const float* eps  = (const float*)d_in[5];
    const float* sg   = (const float*)d_in[6];

    const int B = in_sizes[0] / LSTEPS;   // N_INP == 1
    coesn_kernel<<<B, TPB>>>(x, x2h, h2h, bias, gam, eps, sg, (float*)d_out);
}